// round 15
// baseline (speedup 1.0000x reference)
#include <cuda_runtime.h>
#include <cuda_fp16.h>
#include <cstdint>

// ---------------------------------------------------------------------------
// Problem constants
//   x:      [8, 4096, 512]  fp32
//   w_qkv:  [512, 1536]     fp32
//   out:    [2, 8, 4, 4096, 64] fp32
// g_qkv16 scratch: [32768, 1536] fp16 (q: 0..511, k: 512..1023, v: 1024..1535)
// ---------------------------------------------------------------------------
#define B_      8
#define NTOK    4096
#define DIM     512
#define QKVC    1536
#define NT_     16
#define S_      256
#define H2_     4
#define DH      64
#define M_TOT   (B_ * NTOK)          // 32768

__device__ __half g_qkv16[(size_t)M_TOT * QKVC];    // 100 MB
__device__ __half g_A[(size_t)M_TOT * DIM];         // 32 MB  [M, 512] fp16
__device__ __half g_B[(size_t)QKVC * DIM];          // 1.5 MB [N, 512] fp16 (K-major)
__device__ int    g_sync[256];                      // per-M-tile GEMM completion

// ===========================================================================
// helpers
// ===========================================================================
__device__ __forceinline__ uint32_t smem_u32(const void* p) {
    uint32_t a;
    asm("{ .reg .u64 t; cvta.to.shared.u64 t, %1; cvt.u32.u64 %0, t; }"
        : "=r"(a) : "l"(p));
    return a;
}

#define SMEM_SWIZZLE_128B(byte_offset) \
    ((byte_offset) ^ (((byte_offset) >> 3) & 0x70))

__device__ __forceinline__ void ldsm_x4(uint32_t* r, uint32_t addr) {
    asm volatile("ldmatrix.sync.aligned.m8n8.x4.shared.b16 {%0,%1,%2,%3}, [%4];"
        : "=r"(r[0]), "=r"(r[1]), "=r"(r[2]), "=r"(r[3]) : "r"(addr));
}

__device__ __forceinline__ void ldsm_x4_t(uint32_t* r, uint32_t addr) {
    asm volatile("ldmatrix.sync.aligned.m8n8.x4.trans.shared.b16 {%0,%1,%2,%3}, [%4];"
        : "=r"(r[0]), "=r"(r[1]), "=r"(r[2]), "=r"(r[3]) : "r"(addr));
}

__device__ __forceinline__ void mma16816(float* d, const uint32_t* a,
                                         uint32_t b0, uint32_t b1) {
    asm volatile(
        "mma.sync.aligned.m16n8k16.row.col.f32.f16.f16.f32 "
        "{%0,%1,%2,%3}, {%4,%5,%6,%7}, {%8,%9}, {%0,%1,%2,%3};"
        : "+f"(d[0]), "+f"(d[1]), "+f"(d[2]), "+f"(d[3])
        : "r"(a[0]), "r"(a[1]), "r"(a[2]), "r"(a[3]), "r"(b0), "r"(b1));
}

__device__ __forceinline__ uint32_t pack_h2(float a, float b) {
    __half2 h = __floats2half2_rn(a, b);
    return *(uint32_t*)&h;
}

// ===========================================================================
// Fused conversion: fp32 -> fp16  (+ zero the sync flags from block 0)
//   blocks [0, 8192):     A  (x [M,512] -> g_A, 8 elems/thread)
//   blocks [8192, 8384):  B  (w [512,1536] -> g_B [1536,512], smem transpose)
// ===========================================================================
#define NA_BLK2 8192
#define NB_TIL  192     // 8 k-tiles x 24 n-tiles of 64x64

__global__ void __launch_bounds__(256)
conv_ab(const float* __restrict__ x, const float* __restrict__ w)
{
    __shared__ __half st[64][72];
    const int tid = threadIdx.x;
    const int bidx = blockIdx.x;

    if (bidx == 0) g_sync[tid] = 0;   // reset flags for this graph replay

    if (bidx < NA_BLK2) {
        size_t idx = (size_t)bidx * 256 + tid;      // 0 .. 2097151
        size_t m = idx >> 6;
        int seg = (int)(idx & 63) * 8;
        const float* src = x + m * DIM + seg;
        float4 v0 = *(const float4*)(src);
        float4 v1 = *(const float4*)(src + 4);
        __align__(16) __half h[8];
        h[0] = __float2half_rn(v0.x); h[1] = __float2half_rn(v0.y);
        h[2] = __float2half_rn(v0.z); h[3] = __float2half_rn(v0.w);
        h[4] = __float2half_rn(v1.x); h[5] = __float2half_rn(v1.y);
        h[6] = __float2half_rn(v1.z); h[7] = __float2half_rn(v1.w);
        *(uint4*)&g_A[m * DIM + seg] = *(uint4*)h;
    } else {
        const int tb = bidx - NA_BLK2;
        const int kt = tb & 7;        // k tile (8 of 64)
        const int nt = tb >> 3;       // n tile (24 of 64)
        #pragma unroll
        for (int it = 0; it < 4; it++) {
            const int row  = it * 16 + (tid >> 4);
            const int col4 = (tid & 15) * 4;
            float4 v = *(const float4*)(w + (size_t)(kt * 64 + row) * QKVC + nt * 64 + col4);
            st[col4 + 0][row] = __float2half_rn(v.x);
            st[col4 + 1][row] = __float2half_rn(v.y);
            st[col4 + 2][row] = __float2half_rn(v.z);
            st[col4 + 3][row] = __float2half_rn(v.w);
        }
        __syncthreads();
        #pragma unroll
        for (int it = 0; it < 2; it++) {
            const int n    = it * 32 + (tid >> 3);
            const int koff = (tid & 7) * 8;
            uint4 val = *(const uint4*)&st[n][koff];
            *(uint4*)&g_B[(size_t)(nt * 64 + n) * DIM + kt * 64 + koff] = val;
        }
    }
}

// ===========================================================================
// MEGA kernel: GEMM blocks [0,3072), attention tail [3072,4096).
//   GEMM: 128x128 tile, warp tile 32x64, 3-stage cp.async, fully-unrolled
//         mainloop with software-pipelined (double-buffered) A/B fragments.
//   Attention: waits on g_sync for its two M-tiles; Q/K/V staged in smem.
// ===========================================================================
#define STAGES 3
#define CHUNKS 8
#define KC 64
#define STAGE_BYTES 32768   // A tile 16KB + B tile 16KB
#define GEMM_BLOCKS 3072

__global__ void __launch_bounds__(256, 2)
mega(float* __restrict__ out)
{
    extern __shared__ __align__(128) char dsm_raw[];
    const int tid  = threadIdx.x;
    const int bid  = blockIdx.x;

    if (bid < GEMM_BLOCKS) {
        // =============================== GEMM ===============================
        const uint32_t tile_base = smem_u32(dsm_raw);
        const int wid  = tid >> 5;
        const int lane = tid & 31;
        const int wm = wid & 3;
        const int wn = wid >> 2;
        const int by = bid / 12;
        const int bx = bid - by * 12;

        const size_t m0 = (size_t)by * 128;
        const size_t n0 = (size_t)bx * 128;

        const int ldRow  = tid >> 1;
        const int ldCol0 = (tid & 1) * 64;

        auto load_chunk = [&](int c, int s) {
            const int kk = c * KC;
            const uint32_t abase = tile_base + s * STAGE_BYTES;
            const uint32_t bbase = abase + 16384;
            const __half* srcA = g_A + (m0 + ldRow) * DIM + kk + ldCol0 / 2;
            const __half* srcB = g_B + (n0 + ldRow) * DIM + kk + ldCol0 / 2;
            #pragma unroll
            for (int i = 0; i < 4; i++) {
                const uint32_t off = SMEM_SWIZZLE_128B((uint32_t)(ldRow * 128 + ldCol0 + i * 16));
                asm volatile("cp.async.cg.shared.global [%0], [%1], 16;"
                             :: "r"(abase + off), "l"(srcA + i * 8) : "memory");
                asm volatile("cp.async.cg.shared.global [%0], [%1], 16;"
                             :: "r"(bbase + off), "l"(srcB + i * 8) : "memory");
            }
        };

        float acc[2][8][4];
        #pragma unroll
        for (int mf = 0; mf < 2; mf++)
            #pragma unroll
            for (int nf = 0; nf < 8; nf++)
                #pragma unroll
                for (int i = 0; i < 4; i++) acc[mf][nf][i] = 0.f;

        load_chunk(0, 0);
        asm volatile("cp.async.commit_group;" ::: "memory");
        load_chunk(1, 1);
        asm volatile("cp.async.commit_group;" ::: "memory");

        const int lrow  = lane & 15;
        const int lhalf = (lane >> 4) * 16;
        const uint32_t arow0 = (uint32_t)(wm * 32 + lrow) * 128;
        const uint32_t arow1 = (uint32_t)(wm * 32 + 16 + lrow) * 128;

        // fully unrolled + software-pipelined fragment loads:
        // kf double-buffered across nq, afr double-buffered across k16.
        #pragma unroll
        for (int c = 0; c < CHUNKS; c++) {
            asm volatile("cp.async.wait_group 1;" ::: "memory");
            __syncthreads();

            if (c + 2 < CHUNKS) load_chunk(c + 2, (c + 2) % STAGES);
            asm volatile("cp.async.commit_group;" ::: "memory");

            const uint32_t abase = tile_base + (c % STAGES) * STAGE_BYTES;
            const uint32_t bbase = abase + 16384;

            uint32_t afr[2][2][4];   // [k16 parity][mf][regs]
            uint32_t kf[2][4];       // [nq parity][regs]

            // preload k16=0 fragments
            {
                const uint32_t colb = (uint32_t)lhalf;
                ldsm_x4(afr[0][0], abase + SMEM_SWIZZLE_128B(arow0 + colb));
                ldsm_x4(afr[0][1], abase + SMEM_SWIZZLE_128B(arow1 + colb));
                ldsm_x4(kf[0], bbase + SMEM_SWIZZLE_128B(
                    (uint32_t)(wn * 64 + lrow) * 128 + colb));
            }

            #pragma unroll
            for (int k16 = 0; k16 < 4; k16++) {
                const int p = k16 & 1;
                const uint32_t colb  = (uint32_t)(k16 * 32 + lhalf);
                const uint32_t colbn = (uint32_t)((k16 + 1) * 32 + lhalf);
                #pragma unroll
                for (int nq = 0; nq < 4; nq++) {
                    const int cur = nq & 1;
                    if (nq < 3) {
                        // prefetch next B fragment of this k16
                        ldsm_x4(kf[cur ^ 1], bbase + SMEM_SWIZZLE_128B(
                            (uint32_t)(wn * 64 + (nq + 1) * 16 + lrow) * 128 + colb));
                    } else if (k16 < 3) {
                        // prefetch next k16's A fragments + first B fragment
                        ldsm_x4(afr[p ^ 1][0], abase + SMEM_SWIZZLE_128B(arow0 + colbn));
                        ldsm_x4(afr[p ^ 1][1], abase + SMEM_SWIZZLE_128B(arow1 + colbn));
                        ldsm_x4(kf[cur ^ 1], bbase + SMEM_SWIZZLE_128B(
                            (uint32_t)(wn * 64 + lrow) * 128 + colbn));
                    }
                    mma16816(acc[0][2 * nq + 0], afr[p][0], kf[cur][0], kf[cur][2]);
                    mma16816(acc[0][2 * nq + 1], afr[p][0], kf[cur][1], kf[cur][3]);
                    mma16816(acc[1][2 * nq + 0], afr[p][1], kf[cur][0], kf[cur][2]);
                    mma16816(acc[1][2 * nq + 1], afr[p][1], kf[cur][1], kf[cur][3]);
                }
            }
        }

        const int qrow = lane >> 2;
        const int qcol = (lane & 3) * 2;
        #pragma unroll
        for (int mf = 0; mf < 2; mf++) {
            const size_t r0 = m0 + wm * 32 + mf * 16 + qrow;
            #pragma unroll
            for (int nf = 0; nf < 8; nf++) {
                const size_t cidx = n0 + wn * 64 + nf * 8 + qcol;
                *(__half2*)(g_qkv16 + r0 * QKVC + cidx) =
                    __floats2half2_rn(acc[mf][nf][0], acc[mf][nf][1]);
                *(__half2*)(g_qkv16 + (r0 + 8) * QKVC + cidx) =
                    __floats2half2_rn(acc[mf][nf][2], acc[mf][nf][3]);
            }
        }

        // signal completion of this (by, bx) tile
        __threadfence();
        __syncthreads();
        if (tid == 0) atomicAdd(&g_sync[by], 1);
        return;
    }

    // =============================== attention ===============================
    const uint32_t qs = smem_u32(dsm_raw);
    const uint32_t ks = qs + 32768;
    const uint32_t vs = qs + 65536;

    const int warp = tid >> 5, lane = tid & 31;
    const int lrow  = lane & 15;
    const int lhalf = (lane >> 4) * 16;
    const int gp = bid - GEMM_BLOCKS;           // 0..1023
    const bool is_spatial = gp < 512;
    const int g  = is_spatial ? gp : gp - 512;
    const int c0 = g & 15;
    const int h  = (g >> 4) & 3;
    const int b  = g >> 6;

    // wait for the two producing M-tiles (12 N-tiles each)
    {
        const int by0 = b * 32 + c0 * 2;
        if (tid == 0) {
            volatile int* f = g_sync;
            while (f[by0] != 12)     __nanosleep(64);
            while (f[by0 + 1] != 12) __nanosleep(64);
            __threadfence();
        }
        __syncthreads();
    }

    // cooperative Q/K/V tile load
    {
        const int hoff = is_spatial ? h * DH : (4 + h) * DH;
        const __half* src = g_qkv16 + ((size_t)b * NTOK + (size_t)c0 * S_ + tid) * QKVC + hoff;
        #pragma unroll
        for (int i = 0; i < 8; i++) {
            const uint32_t off = SMEM_SWIZZLE_128B((uint32_t)(tid * 128 + i * 16));
            asm volatile("cp.async.cg.shared.global [%0], [%1], 16;"
                         :: "r"(qs + off), "l"(src + i * 8) : "memory");
            asm volatile("cp.async.cg.shared.global [%0], [%1], 16;"
                         :: "r"(ks + off), "l"(src + 512 + i * 8) : "memory");
            asm volatile("cp.async.cg.shared.global [%0], [%1], 16;"
                         :: "r"(vs + off), "l"(src + 1024 + i * 8) : "memory");
        }
        asm volatile("cp.async.commit_group;" ::: "memory");
        asm volatile("cp.async.wait_group 0;" ::: "memory");
        __syncthreads();
    }

    if (is_spatial) {
        // -------- spatial: 256x256, strips processed sequentially --------
        const int m0 = warp * 32;
        const size_t obase = (((size_t)b * H2_ + h) * NTOK + (size_t)c0 * S_) * DH;

        #pragma unroll 1
        for (int st = 0; st < 2; st++) {
            const int gb = m0 + st * 16;

            uint32_t aq[4][4];
            #pragma unroll
            for (int k16 = 0; k16 < 4; k16++)
                ldsm_x4(aq[k16], qs + SMEM_SWIZZLE_128B(
                    (uint32_t)(gb + lrow) * 128 + k16 * 32 + lhalf));

            float o[8][4];
            #pragma unroll
            for (int nt = 0; nt < 8; nt++)
                #pragma unroll
                for (int i = 0; i < 4; i++) o[nt][i] = 0.f;
            float l0 = 0.f, l1 = 0.f;

            #pragma unroll 1
            for (int c = 0; c < 4; c++) {
                const int k0 = c * 64;

                float s[8][4];
                #pragma unroll
                for (int nt = 0; nt < 8; nt++)
                    #pragma unroll
                    for (int i = 0; i < 4; i++) s[nt][i] = 0.f;

                #pragma unroll
                for (int k16 = 0; k16 < 4; k16++) {
                    const uint32_t colb = (uint32_t)(k16 * 32 + lhalf);
                    #pragma unroll
                    for (int kg = 0; kg < 4; kg++) {
                        uint32_t kf[4];
                        ldsm_x4(kf, ks + SMEM_SWIZZLE_128B(
                            (uint32_t)(k0 + kg * 16 + lrow) * 128 + colb));
                        mma16816(s[2 * kg + 0], aq[k16], kf[0], kf[2]);
                        mma16816(s[2 * kg + 1], aq[k16], kf[1], kf[3]);
                    }
                }

                uint32_t pa[4][4];
                #pragma unroll
                for (int nt = 0; nt < 8; nt++) {
                    const float p0 = __expf(s[nt][0] * 0.125f);
                    const float p1 = __expf(s[nt][1] * 0.125f);
                    const float p2 = __expf(s[nt][2] * 0.125f);
                    const float p3 = __expf(s[nt][3] * 0.125f);
                    l0 += p0 + p1;
                    l1 += p2 + p3;
                    const int kk = nt >> 1;
                    if (nt & 1) {
                        pa[kk][2] = pack_h2(p0, p1);
                        pa[kk][3] = pack_h2(p2, p3);
                    } else {
                        pa[kk][0] = pack_h2(p0, p1);
                        pa[kk][1] = pack_h2(p2, p3);
                    }
                }

                #pragma unroll
                for (int k16 = 0; k16 < 4; k16++) {
                    const uint32_t vrow = (uint32_t)(k0 + k16 * 16 + lrow);
                    #pragma unroll
                    for (int j = 0; j < 4; j++) {
                        uint32_t r[4];
                        ldsm_x4_t(r, vs + SMEM_SWIZZLE_128B(vrow * 128 + j * 32 + lhalf));
                        mma16816(o[2 * j + 0], pa[k16], r[0], r[1]);
                        mma16816(o[2 * j + 1], pa[k16], r[2], r[3]);
                    }
                }
            }

            l0 += __shfl_xor_sync(0xffffffffu, l0, 1);
            l0 += __shfl_xor_sync(0xffffffffu, l0, 2);
            l1 += __shfl_xor_sync(0xffffffffu, l1, 1);
            l1 += __shfl_xor_sync(0xffffffffu, l1, 2);

            const float inv0 = 1.f / l0;
            const float inv1 = 1.f / l1;
            const int rlo = gb + (lane >> 2);
            #pragma unroll
            for (int nt = 0; nt < 8; nt++) {
                const int col = nt * 8 + (lane & 3) * 2;
                *(float2*)(out + obase + (size_t)rlo * DH + col) =
                    make_float2(o[nt][0] * inv0, o[nt][1] * inv0);
                *(float2*)(out + obase + (size_t)(rlo + 8) * DH + col) =
                    make_float2(o[nt][2] * inv1, o[nt][3] * inv1);
            }
        }
    } else {
        // ------------- temporal: 16 independent 16x16 attentions -------------
        const int m0 = warp * 32;
        const size_t obase = ((((size_t)8 + b) * H2_ + h) * NTOK + (size_t)c0 * S_) * DH;

        #pragma unroll 1
        for (int st = 0; st < 2; st++) {
            const int gbase = m0 + st * 16;
            const uint32_t grow = (uint32_t)(gbase + lrow);

            float s[2][4] = {{0.f, 0.f, 0.f, 0.f}, {0.f, 0.f, 0.f, 0.f}};
            uint32_t pa[4];
            #pragma unroll
            for (int k16 = 0; k16 < 4; k16++) {
                uint32_t aq[4], kf[4];
                const uint32_t colb = (uint32_t)(k16 * 32 + lhalf);
                ldsm_x4(aq, qs + SMEM_SWIZZLE_128B(grow * 128 + colb));
                ldsm_x4(kf, ks + SMEM_SWIZZLE_128B(grow * 128 + colb));
                mma16816(s[0], aq, kf[0], kf[2]);
                mma16816(s[1], aq, kf[1], kf[3]);
            }

            float l0 = 0.f, l1 = 0.f;
            #pragma unroll
            for (int nt = 0; nt < 2; nt++) {
                const float p0 = __expf(s[nt][0] * 0.125f);
                const float p1 = __expf(s[nt][1] * 0.125f);
                const float p2 = __expf(s[nt][2] * 0.125f);
                const float p3 = __expf(s[nt][3] * 0.125f);
                l0 += p0 + p1;
                l1 += p2 + p3;
                pa[2 * nt + 0] = pack_h2(p0, p1);
                pa[2 * nt + 1] = pack_h2(p2, p3);
            }
            l0 += __shfl_xor_sync(0xffffffffu, l0, 1);
            l0 += __shfl_xor_sync(0xffffffffu, l0, 2);
            l1 += __shfl_xor_sync(0xffffffffu, l1, 1);
            l1 += __shfl_xor_sync(0xffffffffu, l1, 2);

            float o[8][4];
            #pragma unroll
            for (int nt = 0; nt < 8; nt++)
                #pragma unroll
                for (int i = 0; i < 4; i++) o[nt][i] = 0.f;
            #pragma unroll
            for (int j = 0; j < 4; j++) {
                uint32_t r[4];
                ldsm_x4_t(r, vs + SMEM_SWIZZLE_128B(grow * 128 + j * 32 + lhalf));
                mma16816(o[2 * j + 0], pa, r[0], r[1]);
                mma16816(o[2 * j + 1], pa, r[2], r[3]);
            }

            const float inv0 = 1.f / l0;
            const float inv1 = 1.f / l1;
            const int rlo = gbase + (lane >> 2);
            #pragma unroll
            for (int nt = 0; nt < 8; nt++) {
                const int col = nt * 8 + (lane & 3) * 2;
                *(float2*)(out + obase + (size_t)rlo * DH + col) =
                    make_float2(o[nt][0] * inv0, o[nt][1] * inv0);
                *(float2*)(out + obase + (size_t)(rlo + 8) * DH + col) =
                    make_float2(o[nt][2] * inv1, o[nt][3] * inv1);
            }
        }
    }
}

// ---------------------------------------------------------------------------
extern "C" void kernel_launch(void* const* d_in, const int* in_sizes, int n_in,
                              void* d_out, int out_size)
{
    const float* x = (const float*)d_in[0];   // [8,4096,512]
    const float* w = (const float*)d_in[1];   // [512,1536]
    float* out = (float*)d_out;               // [2,8,4,4096,64]

    // 0) fp32 -> fp16 + flag reset (standalone, high occupancy)
    conv_ab<<<NA_BLK2 + NB_TIL, 256>>>(x, w);

    // 1) mega: GEMM (blocks 0..3071) + attention tail (3072..4095), overlapped
    const int mega_smem = STAGES * STAGE_BYTES;          // 98304
    cudaFuncSetAttribute(mega, cudaFuncAttributeMaxDynamicSharedMemorySize, mega_smem);
    mega<<<GEMM_BLOCKS + 1024, 256, mega_smem>>>(out);
}

// round 16
// speedup vs baseline: 1.2825x; 1.2825x over previous
#include <cuda_runtime.h>
#include <cuda_fp16.h>
#include <cstdint>

// ---------------------------------------------------------------------------
// Problem constants
//   x:      [8, 4096, 512]  fp32
//   w_qkv:  [512, 1536]     fp32
//   out:    [2, 8, 4, 4096, 64] fp32
// g_qkv16 scratch: [32768, 1536] fp16 (q: 0..511, k: 512..1023, v: 1024..1535)
// ---------------------------------------------------------------------------
#define B_      8
#define NTOK    4096
#define DIM     512
#define QKVC    1536
#define NT_     16
#define S_      256
#define H2_     4
#define DH      64
#define M_TOT   (B_ * NTOK)          // 32768

__device__ __half g_qkv16[(size_t)M_TOT * QKVC];    // 100 MB
__device__ __half g_A[(size_t)M_TOT * DIM];         // 32 MB  [M, 512] fp16
__device__ __half g_B[(size_t)QKVC * DIM];          // 1.5 MB [N, 512] fp16 (K-major)
__device__ int    g_sync[256 * 12];                 // per-(M-tile, N-tile) done flag

// ===========================================================================
// helpers
// ===========================================================================
__device__ __forceinline__ uint32_t smem_u32(const void* p) {
    uint32_t a;
    asm("{ .reg .u64 t; cvta.to.shared.u64 t, %1; cvt.u32.u64 %0, t; }"
        : "=r"(a) : "l"(p));
    return a;
}

#define SMEM_SWIZZLE_128B(byte_offset) \
    ((byte_offset) ^ (((byte_offset) >> 3) & 0x70))

__device__ __forceinline__ void ldsm_x4(uint32_t* r, uint32_t addr) {
    asm volatile("ldmatrix.sync.aligned.m8n8.x4.shared.b16 {%0,%1,%2,%3}, [%4];"
        : "=r"(r[0]), "=r"(r[1]), "=r"(r[2]), "=r"(r[3]) : "r"(addr));
}

__device__ __forceinline__ void ldsm_x4_t(uint32_t* r, uint32_t addr) {
    asm volatile("ldmatrix.sync.aligned.m8n8.x4.trans.shared.b16 {%0,%1,%2,%3}, [%4];"
        : "=r"(r[0]), "=r"(r[1]), "=r"(r[2]), "=r"(r[3]) : "r"(addr));
}

__device__ __forceinline__ void mma16816(float* d, const uint32_t* a,
                                         uint32_t b0, uint32_t b1) {
    asm volatile(
        "mma.sync.aligned.m16n8k16.row.col.f32.f16.f16.f32 "
        "{%0,%1,%2,%3}, {%4,%5,%6,%7}, {%8,%9}, {%0,%1,%2,%3};"
        : "+f"(d[0]), "+f"(d[1]), "+f"(d[2]), "+f"(d[3])
        : "r"(a[0]), "r"(a[1]), "r"(a[2]), "r"(a[3]), "r"(b0), "r"(b1));
}

__device__ __forceinline__ uint32_t pack_h2(float a, float b) {
    __half2 h = __floats2half2_rn(a, b);
    return *(uint32_t*)&h;
}

// ===========================================================================
// Fused conversion: fp32 -> fp16  (+ zero the sync flags from block 0)
//   blocks [0, 8192):     A  (x [M,512] -> g_A, 8 elems/thread)
//   blocks [8192, 8384):  B  (w [512,1536] -> g_B [1536,512], smem transpose)
// ===========================================================================
#define NA_BLK2 8192
#define NB_TIL  192     // 8 k-tiles x 24 n-tiles of 64x64

__global__ void __launch_bounds__(256)
conv_ab(const float* __restrict__ x, const float* __restrict__ w)
{
    __shared__ __half st[64][72];
    const int tid = threadIdx.x;
    const int bidx = blockIdx.x;

    if (bidx == 0) {
        #pragma unroll
        for (int i = 0; i < 12; i++) g_sync[tid * 12 + i] = 0;   // reset flags
    }

    if (bidx < NA_BLK2) {
        size_t idx = (size_t)bidx * 256 + tid;      // 0 .. 2097151
        size_t m = idx >> 6;
        int seg = (int)(idx & 63) * 8;
        const float* src = x + m * DIM + seg;
        float4 v0 = *(const float4*)(src);
        float4 v1 = *(const float4*)(src + 4);
        __align__(16) __half h[8];
        h[0] = __float2half_rn(v0.x); h[1] = __float2half_rn(v0.y);
        h[2] = __float2half_rn(v0.z); h[3] = __float2half_rn(v0.w);
        h[4] = __float2half_rn(v1.x); h[5] = __float2half_rn(v1.y);
        h[6] = __float2half_rn(v1.z); h[7] = __float2half_rn(v1.w);
        *(uint4*)&g_A[m * DIM + seg] = *(uint4*)h;
    } else {
        const int tb = bidx - NA_BLK2;
        const int kt = tb & 7;        // k tile (8 of 64)
        const int nt = tb >> 3;       // n tile (24 of 64)
        #pragma unroll
        for (int it = 0; it < 4; it++) {
            const int row  = it * 16 + (tid >> 4);
            const int col4 = (tid & 15) * 4;
            float4 v = *(const float4*)(w + (size_t)(kt * 64 + row) * QKVC + nt * 64 + col4);
            st[col4 + 0][row] = __float2half_rn(v.x);
            st[col4 + 1][row] = __float2half_rn(v.y);
            st[col4 + 2][row] = __float2half_rn(v.z);
            st[col4 + 3][row] = __float2half_rn(v.w);
        }
        __syncthreads();
        #pragma unroll
        for (int it = 0; it < 2; it++) {
            const int n    = it * 32 + (tid >> 3);
            const int koff = (tid & 7) * 8;
            uint4 val = *(const uint4*)&st[n][koff];
            *(uint4*)&g_B[(size_t)(nt * 64 + n) * DIM + kt * 64 + koff] = val;
        }
    }
}

// ===========================================================================
// MEGA kernel (R14 structure): GEMM blocks [0,3072), attention tail [3072,4096).
//   GEMM: 128x128 tile, warp tile 32x64, 3-stage cp.async, JIT B-fragments,
//         fully-unrolled 8-chunk mainloop (compile-time stage indices).
//   Attention: waits only on the 6 producing (M-tile, N-tile) flags it needs
//         (Q/K/V tiles of its head), then runs as in R14.
// ===========================================================================
#define STAGES 3
#define CHUNKS 8
#define KC 64
#define STAGE_BYTES 32768   // A tile 16KB + B tile 16KB
#define GEMM_BLOCKS 3072

__global__ void __launch_bounds__(256, 2)
mega(float* __restrict__ out)
{
    extern __shared__ __align__(128) char dsm_raw[];
    const int tid  = threadIdx.x;
    const int bid  = blockIdx.x;

    if (bid < GEMM_BLOCKS) {
        // =============================== GEMM ===============================
        const uint32_t tile_base = smem_u32(dsm_raw);
        const int wid  = tid >> 5;
        const int lane = tid & 31;
        const int wm = wid & 3;
        const int wn = wid >> 2;
        const int by = bid / 12;
        const int bx = bid - by * 12;

        const size_t m0 = (size_t)by * 128;
        const size_t n0 = (size_t)bx * 128;

        const int ldRow  = tid >> 1;
        const int ldCol0 = (tid & 1) * 64;

        auto load_chunk = [&](int c, int s) {
            const int kk = c * KC;
            const uint32_t abase = tile_base + s * STAGE_BYTES;
            const uint32_t bbase = abase + 16384;
            const __half* srcA = g_A + (m0 + ldRow) * DIM + kk + ldCol0 / 2;
            const __half* srcB = g_B + (n0 + ldRow) * DIM + kk + ldCol0 / 2;
            #pragma unroll
            for (int i = 0; i < 4; i++) {
                const uint32_t off = SMEM_SWIZZLE_128B((uint32_t)(ldRow * 128 + ldCol0 + i * 16));
                asm volatile("cp.async.cg.shared.global [%0], [%1], 16;"
                             :: "r"(abase + off), "l"(srcA + i * 8) : "memory");
                asm volatile("cp.async.cg.shared.global [%0], [%1], 16;"
                             :: "r"(bbase + off), "l"(srcB + i * 8) : "memory");
            }
        };

        float acc[2][8][4];
        #pragma unroll
        for (int mf = 0; mf < 2; mf++)
            #pragma unroll
            for (int nf = 0; nf < 8; nf++)
                #pragma unroll
                for (int i = 0; i < 4; i++) acc[mf][nf][i] = 0.f;

        load_chunk(0, 0);
        asm volatile("cp.async.commit_group;" ::: "memory");
        load_chunk(1, 1);
        asm volatile("cp.async.commit_group;" ::: "memory");

        const int lrow  = lane & 15;
        const int lhalf = (lane >> 4) * 16;

        // fully unrolled mainloop: stage indices and tail branch are
        // compile-time; removes per-chunk div/mod + branch from hot path
        #pragma unroll
        for (int c = 0; c < CHUNKS; c++) {
            asm volatile("cp.async.wait_group 1;" ::: "memory");
            __syncthreads();

            if (c + 2 < CHUNKS) load_chunk(c + 2, (c + 2) % STAGES);
            asm volatile("cp.async.commit_group;" ::: "memory");

            const uint32_t abase = tile_base + (c % STAGES) * STAGE_BYTES;
            const uint32_t bbase = abase + 16384;

            #pragma unroll
            for (int k16 = 0; k16 < 4; k16++) {
                const uint32_t colb = (uint32_t)(k16 * 32 + lhalf);
                uint32_t afr[2][4];
                #pragma unroll
                for (int mf = 0; mf < 2; mf++) {
                    const uint32_t row = (uint32_t)(wm * 32 + mf * 16 + lrow);
                    ldsm_x4(afr[mf], abase + SMEM_SWIZZLE_128B(row * 128 + colb));
                }
                // B fragments loaded just-in-time (register pressure relief)
                #pragma unroll
                for (int nq = 0; nq < 4; nq++) {
                    uint32_t kf[4];
                    const uint32_t row = (uint32_t)(wn * 64 + nq * 16 + lrow);
                    ldsm_x4(kf, bbase + SMEM_SWIZZLE_128B(row * 128 + colb));
                    #pragma unroll
                    for (int mf = 0; mf < 2; mf++) {
                        mma16816(acc[mf][2 * nq + 0], afr[mf], kf[0], kf[2]);
                        mma16816(acc[mf][2 * nq + 1], afr[mf], kf[1], kf[3]);
                    }
                }
            }
        }

        const int qrow = lane >> 2;
        const int qcol = (lane & 3) * 2;
        #pragma unroll
        for (int mf = 0; mf < 2; mf++) {
            const size_t r0 = m0 + wm * 32 + mf * 16 + qrow;
            #pragma unroll
            for (int nf = 0; nf < 8; nf++) {
                const size_t cidx = n0 + wn * 64 + nf * 8 + qcol;
                *(__half2*)(g_qkv16 + r0 * QKVC + cidx) =
                    __floats2half2_rn(acc[mf][nf][0], acc[mf][nf][1]);
                *(__half2*)(g_qkv16 + (r0 + 8) * QKVC + cidx) =
                    __floats2half2_rn(acc[mf][nf][2], acc[mf][nf][3]);
            }
        }

        // signal completion of this (by, bx) tile
        __threadfence();
        __syncthreads();
        if (tid == 0) atomicExch(&g_sync[by * 12 + bx], 1);
        return;
    }

    // =============================== attention ===============================
    const uint32_t qs = smem_u32(dsm_raw);
    const uint32_t ks = qs + 32768;
    const uint32_t vs = qs + 65536;

    const int warp = tid >> 5, lane = tid & 31;
    const int lrow  = lane & 15;
    const int lhalf = (lane >> 4) * 16;
    const int gp = bid - GEMM_BLOCKS;           // 0..1023
    const bool is_spatial = gp < 512;
    const int g  = is_spatial ? gp : gp - 512;
    const int c0 = g & 15;
    const int h  = (g >> 4) & 3;
    const int b  = g >> 6;
    const int hoff = is_spatial ? h * DH : (4 + h) * DH;

    // wait only for the 6 producing (M-tile, N-tile) flags: Q/K/V tiles of
    // this head in each of the two M-tiles
    {
        const int by0 = b * 32 + c0 * 2;
        const int tq = (hoff / DH) >> 1;        // N-tile of Q head (0..3)
        if (tid == 0) {
            volatile int* f = g_sync;
            #pragma unroll
            for (int m = 0; m < 2; m++) {
                const int base = (by0 + m) * 12;
                while (!f[base + tq])     __nanosleep(64);
                while (!f[base + 4 + tq]) __nanosleep(64);
                while (!f[base + 8 + tq]) __nanosleep(64);
            }
            __threadfence();
        }
        __syncthreads();
    }

    // cooperative Q/K/V tile load
    {
        const __half* src = g_qkv16 + ((size_t)b * NTOK + (size_t)c0 * S_ + tid) * QKVC + hoff;
        #pragma unroll
        for (int i = 0; i < 8; i++) {
            const uint32_t off = SMEM_SWIZZLE_128B((uint32_t)(tid * 128 + i * 16));
            asm volatile("cp.async.cg.shared.global [%0], [%1], 16;"
                         :: "r"(qs + off), "l"(src + i * 8) : "memory");
            asm volatile("cp.async.cg.shared.global [%0], [%1], 16;"
                         :: "r"(ks + off), "l"(src + 512 + i * 8) : "memory");
            asm volatile("cp.async.cg.shared.global [%0], [%1], 16;"
                         :: "r"(vs + off), "l"(src + 1024 + i * 8) : "memory");
        }
        asm volatile("cp.async.commit_group;" ::: "memory");
        asm volatile("cp.async.wait_group 0;" ::: "memory");
        __syncthreads();
    }

    if (is_spatial) {
        // -------- spatial: 256x256, strips processed sequentially --------
        const int m0 = warp * 32;
        const size_t obase = (((size_t)b * H2_ + h) * NTOK + (size_t)c0 * S_) * DH;

        #pragma unroll 1
        for (int st = 0; st < 2; st++) {
            const int gb = m0 + st * 16;

            uint32_t aq[4][4];
            #pragma unroll
            for (int k16 = 0; k16 < 4; k16++)
                ldsm_x4(aq[k16], qs + SMEM_SWIZZLE_128B(
                    (uint32_t)(gb + lrow) * 128 + k16 * 32 + lhalf));

            float o[8][4];
            #pragma unroll
            for (int nt = 0; nt < 8; nt++)
                #pragma unroll
                for (int i = 0; i < 4; i++) o[nt][i] = 0.f;
            float l0 = 0.f, l1 = 0.f;

            #pragma unroll 1
            for (int c = 0; c < 4; c++) {
                const int k0 = c * 64;

                float s[8][4];
                #pragma unroll
                for (int nt = 0; nt < 8; nt++)
                    #pragma unroll
                    for (int i = 0; i < 4; i++) s[nt][i] = 0.f;

                #pragma unroll
                for (int k16 = 0; k16 < 4; k16++) {
                    const uint32_t colb = (uint32_t)(k16 * 32 + lhalf);
                    #pragma unroll
                    for (int kg = 0; kg < 4; kg++) {
                        uint32_t kf[4];
                        ldsm_x4(kf, ks + SMEM_SWIZZLE_128B(
                            (uint32_t)(k0 + kg * 16 + lrow) * 128 + colb));
                        mma16816(s[2 * kg + 0], aq[k16], kf[0], kf[2]);
                        mma16816(s[2 * kg + 1], aq[k16], kf[1], kf[3]);
                    }
                }

                uint32_t pa[4][4];
                #pragma unroll
                for (int nt = 0; nt < 8; nt++) {
                    const float p0 = __expf(s[nt][0] * 0.125f);
                    const float p1 = __expf(s[nt][1] * 0.125f);
                    const float p2 = __expf(s[nt][2] * 0.125f);
                    const float p3 = __expf(s[nt][3] * 0.125f);
                    l0 += p0 + p1;
                    l1 += p2 + p3;
                    const int kk = nt >> 1;
                    if (nt & 1) {
                        pa[kk][2] = pack_h2(p0, p1);
                        pa[kk][3] = pack_h2(p2, p3);
                    } else {
                        pa[kk][0] = pack_h2(p0, p1);
                        pa[kk][1] = pack_h2(p2, p3);
                    }
                }

                #pragma unroll
                for (int k16 = 0; k16 < 4; k16++) {
                    const uint32_t vrow = (uint32_t)(k0 + k16 * 16 + lrow);
                    #pragma unroll
                    for (int j = 0; j < 4; j++) {
                        uint32_t r[4];
                        ldsm_x4_t(r, vs + SMEM_SWIZZLE_128B(vrow * 128 + j * 32 + lhalf));
                        mma16816(o[2 * j + 0], pa[k16], r[0], r[1]);
                        mma16816(o[2 * j + 1], pa[k16], r[2], r[3]);
                    }
                }
            }

            l0 += __shfl_xor_sync(0xffffffffu, l0, 1);
            l0 += __shfl_xor_sync(0xffffffffu, l0, 2);
            l1 += __shfl_xor_sync(0xffffffffu, l1, 1);
            l1 += __shfl_xor_sync(0xffffffffu, l1, 2);

            const float inv0 = 1.f / l0;
            const float inv1 = 1.f / l1;
            const int rlo = gb + (lane >> 2);
            #pragma unroll
            for (int nt = 0; nt < 8; nt++) {
                const int col = nt * 8 + (lane & 3) * 2;
                *(float2*)(out + obase + (size_t)rlo * DH + col) =
                    make_float2(o[nt][0] * inv0, o[nt][1] * inv0);
                *(float2*)(out + obase + (size_t)(rlo + 8) * DH + col) =
                    make_float2(o[nt][2] * inv1, o[nt][3] * inv1);
            }
        }
    } else {
        // ------------- temporal: 16 independent 16x16 attentions -------------
        const int m0 = warp * 32;
        const size_t obase = ((((size_t)8 + b) * H2_ + h) * NTOK + (size_t)c0 * S_) * DH;

        #pragma unroll 1
        for (int st = 0; st < 2; st++) {
            const int gbase = m0 + st * 16;
            const uint32_t grow = (uint32_t)(gbase + lrow);

            float s[2][4] = {{0.f, 0.f, 0.f, 0.f}, {0.f, 0.f, 0.f, 0.f}};
            uint32_t pa[4];
            #pragma unroll
            for (int k16 = 0; k16 < 4; k16++) {
                uint32_t aq[4], kf[4];
                const uint32_t colb = (uint32_t)(k16 * 32 + lhalf);
                ldsm_x4(aq, qs + SMEM_SWIZZLE_128B(grow * 128 + colb));
                ldsm_x4(kf, ks + SMEM_SWIZZLE_128B(grow * 128 + colb));
                mma16816(s[0], aq, kf[0], kf[2]);
                mma16816(s[1], aq, kf[1], kf[3]);
            }

            float l0 = 0.f, l1 = 0.f;
            #pragma unroll
            for (int nt = 0; nt < 2; nt++) {
                const float p0 = __expf(s[nt][0] * 0.125f);
                const float p1 = __expf(s[nt][1] * 0.125f);
                const float p2 = __expf(s[nt][2] * 0.125f);
                const float p3 = __expf(s[nt][3] * 0.125f);
                l0 += p0 + p1;
                l1 += p2 + p3;
                pa[2 * nt + 0] = pack_h2(p0, p1);
                pa[2 * nt + 1] = pack_h2(p2, p3);
            }
            l0 += __shfl_xor_sync(0xffffffffu, l0, 1);
            l0 += __shfl_xor_sync(0xffffffffu, l0, 2);
            l1 += __shfl_xor_sync(0xffffffffu, l1, 1);
            l1 += __shfl_xor_sync(0xffffffffu, l1, 2);

            float o[8][4];
            #pragma unroll
            for (int nt = 0; nt < 8; nt++)
                #pragma unroll
                for (int i = 0; i < 4; i++) o[nt][i] = 0.f;
            #pragma unroll
            for (int j = 0; j < 4; j++) {
                uint32_t r[4];
                ldsm_x4_t(r, vs + SMEM_SWIZZLE_128B(grow * 128 + j * 32 + lhalf));
                mma16816(o[2 * j + 0], pa, r[0], r[1]);
                mma16816(o[2 * j + 1], pa, r[2], r[3]);
            }

            const float inv0 = 1.f / l0;
            const float inv1 = 1.f / l1;
            const int rlo = gbase + (lane >> 2);
            #pragma unroll
            for (int nt = 0; nt < 8; nt++) {
                const int col = nt * 8 + (lane & 3) * 2;
                *(float2*)(out + obase + (size_t)rlo * DH + col) =
                    make_float2(o[nt][0] * inv0, o[nt][1] * inv0);
                *(float2*)(out + obase + (size_t)(rlo + 8) * DH + col) =
                    make_float2(o[nt][2] * inv1, o[nt][3] * inv1);
            }
        }
    }
}

// ---------------------------------------------------------------------------
extern "C" void kernel_launch(void* const* d_in, const int* in_sizes, int n_in,
                              void* d_out, int out_size)
{
    const float* x = (const float*)d_in[0];   // [8,4096,512]
    const float* w = (const float*)d_in[1];   // [512,1536]
    float* out = (float*)d_out;               // [2,8,4,4096,64]

    // 0) fp32 -> fp16 + flag reset (standalone, high occupancy)
    conv_ab<<<NA_BLK2 + NB_TIL, 256>>>(x, w);

    // 1) mega: GEMM (blocks 0..3071) + attention tail (3072..4095), overlapped
    const int mega_smem = STAGES * STAGE_BYTES;          // 98304
    cudaFuncSetAttribute(mega, cudaFuncAttributeMaxDynamicSharedMemorySize, mega_smem);
    mega<<<GEMM_BLOCKS + 1024, 256, mega_smem>>>(out);
}